// round 12
// baseline (speedup 1.0000x reference)
#include <cuda_runtime.h>
#include <cuda_bf16.h>
#include <math_constants.h>
#include <cstdint>

#define Dq 1024
#define Bq 16
#define BM 64
#define BN 32
#define BKB 128                       // K bytes per chunk (full row)
#define NCHUNK (Dq / BKB)             // 8
#define ASTR 144                      // padded row stride (128B + 16B)
#define A_STAGE (BM * ASTR)           // 9216 B
#define B_STAGE (BN * ASTR)           // 4608 B
#define STAGE_BYTES (A_STAGE + B_STAGE)   // 13824 B
#define SMEM_TOTAL (2 * STAGE_BYTES)      // 27648 B
#define NT 128

// ---- scratch (__device__ globals) ------------------------------------------
__device__ uint8_t g_W8 [(size_t)Dq * Dq];            // (64*W)[d][k] e4m3
__device__ uint8_t g_ET8[(size_t)Bq * Dq * Dq];       // E^T[b][n][d] e4m3
__device__ uint8_t g_T8 [(size_t)Bq * Dq * Dq];       // 64*Tt[b][n][d] e4m3
__device__ float g_rowmax[Bq * Dq];

// ---- helpers ---------------------------------------------------------------
__device__ __forceinline__ uint32_t smem_u32(const void* p) {
    uint32_t a;
    asm("{ .reg .u64 t; cvta.to.shared.u64 t, %1; cvt.u32.u64 %0, t; }" : "=r"(a) : "l"(p));
    return a;
}
__device__ __forceinline__ void cp16(uint32_t s, const void* g) {
    asm volatile("cp.async.cg.shared.global [%0], [%1], 16;\n" :: "r"(s), "l"(g));
}
__device__ __forceinline__ void cp_commit() { asm volatile("cp.async.commit_group;\n"); }
template <int N> __device__ __forceinline__ void cp_wait() {
    asm volatile("cp.async.wait_group %0;\n" :: "n"(N));
}
__device__ __forceinline__ void ldsm4(uint32_t* r, uint32_t addr) {
    asm volatile("ldmatrix.sync.aligned.m8n8.x4.shared.b16 {%0,%1,%2,%3}, [%4];"
                 : "=r"(r[0]), "=r"(r[1]), "=r"(r[2]), "=r"(r[3]) : "r"(addr));
}
__device__ __forceinline__ void mma_e4m3(float* d, const uint32_t* a, uint32_t b0, uint32_t b1) {
    asm volatile("mma.sync.aligned.m16n8k32.row.col.f32.e4m3.e4m3.f32 "
                 "{%0,%1,%2,%3}, {%4,%5,%6,%7}, {%8,%9}, {%0,%1,%2,%3};"
                 : "+f"(d[0]), "+f"(d[1]), "+f"(d[2]), "+f"(d[3])
                 : "r"(a[0]), "r"(a[1]), "r"(a[2]), "r"(a[3]), "r"(b0), "r"(b1));
}
__device__ __forceinline__ uint16_t cvt2_e4m3(float hi, float lo) {
    uint16_t r;
    asm("cvt.rn.satfinite.e4m3x2.f32 %0, %1, %2;" : "=h"(r) : "f"(hi), "f"(lo));
    return r;
}
__device__ __forceinline__ void atomicMaxF(float* addr, float val) {
    int old = __float_as_int(*addr);
    while (__int_as_float(old) < val) {
        int assumed = old;
        old = atomicCAS((int*)addr, assumed, __float_as_int(val));
        if (old == assumed) break;
    }
}

// ---- setup kernels ---------------------------------------------------------
__global__ void convert_W_k(const float* __restrict__ W) {
    int i = blockIdx.x * 256 + threadIdx.x;
    float2 v = ((const float2*)W)[i];
    ((uint16_t*)g_W8)[i] = cvt2_e4m3(v.y * 64.f, v.x * 64.f);
    if (i < Bq * Dq) g_rowmax[i] = -CUDART_INF_F;
}
__global__ __launch_bounds__(256) void convert_E_k(const float* __restrict__ E) {
    __shared__ float tile[32][33];
    const int b = blockIdx.z;
    const int x0 = blockIdx.x * 32, y0 = blockIdx.y * 32;
    const float* __restrict__ Eb = E + (size_t)b * Dq * Dq;
    const int t = threadIdx.x;
#pragma unroll
    for (int i = 0; i < 4; i++) {
        int idx = t + i * 256;
        int y = idx >> 5, x = idx & 31;
        tile[y][x] = Eb[(size_t)(y0 + y) * Dq + x0 + x];
    }
    __syncthreads();
    const int n = x0 + (t >> 3);
    const int d0 = (t & 7) * 4;
    float v0 = tile[d0 + 0][t >> 3], v1 = tile[d0 + 1][t >> 3];
    float v2 = tile[d0 + 2][t >> 3], v3 = tile[d0 + 3][t >> 3];
    uint32_t packed = (uint32_t)cvt2_e4m3(v1, v0) | ((uint32_t)cvt2_e4m3(v3, v2) << 16);
    *(uint32_t*)(g_ET8 + (size_t)b * Dq * Dq + (size_t)n * Dq + y0 + d0) = packed;
}

// ---- fp8 tensor-core GEMM ---------------------------------------------------
// 128 threads, warp grid 2(M) x 2(N), warp tile 32 x 16, CTA tile 64 x 32.
// 2-stage double buffer; 8 CTAs/SM (32 warps, 8/SMSP) for stall coverage.
// MODE 0: C = ET[b] @ (64W)^T  -> g_T8 (e4m3)
// MODE 1: C = ET[b] @ T8[b]^T  -> fused rowmax
template <int MODE>
__global__ __launch_bounds__(NT, 8) void fp8_gemm_k() {
    extern __shared__ char smem[];
    const uint32_t sbase = smem_u32(smem);
    const int t = threadIdx.x, lane = t & 31, wid = t >> 5;
    const int wm = wid >> 1, wn = wid & 1;          // 2(M) x 2(N)
    const int b = blockIdx.z;
    const int rowBase = blockIdx.y * BM;
    const int colBase = blockIdx.x * BN;

    const uint8_t* __restrict__ A = g_ET8 + (size_t)b * Dq * Dq;
    const uint8_t* __restrict__ Bm =
        (MODE == 0) ? g_W8 : (g_T8 + (size_t)b * Dq * Dq);

    float acc[2][2][4];
#pragma unroll
    for (int mb = 0; mb < 2; mb++)
#pragma unroll
        for (int nb = 0; nb < 2; nb++)
#pragma unroll
            for (int r = 0; r < 4; r++) acc[mb][nb][r] = 0.f;

    // hoisted fragment smem offsets (within a stage)
    uint32_t aoff[2], boff;
#pragma unroll
    for (int mb = 0; mb < 2; mb++)
        aoff[mb] = (uint32_t)((wm * 32 + mb * 16 + (lane & 15)) * ASTR + (lane >> 4) * 16);
    boff = (uint32_t)((wn * 16 + ((lane >> 4) << 3) + (lane & 7)) * ASTR
                      + ((lane >> 3) & 1) * 16) + A_STAGE;

    // global load pointers: A 4 cp16/thread, B 2 cp16/thread
    const uint8_t* gA = A + (size_t)(rowBase + (t >> 3)) * Dq + (t & 7) * 16;
    const uint8_t* gB = Bm + (size_t)(colBase + (t >> 3)) * Dq + (t & 7) * 16;
    const uint32_t sAof = (uint32_t)((t >> 3) * ASTR + (t & 7) * 16);

    auto load_stage = [&](int c) {
        const uint32_t sS = sbase + (uint32_t)((c & 1) * STAGE_BYTES);
        const size_t k0 = (size_t)c * BKB;
#pragma unroll
        for (int i = 0; i < 4; i++)                 // A: 64 rows x 8 x 16B
            cp16(sS + sAof + (uint32_t)(i * 16 * ASTR), gA + k0 + (size_t)(i * 16) * Dq);
#pragma unroll
        for (int i = 0; i < 2; i++)                 // B: 32 rows x 8 x 16B
            cp16(sS + A_STAGE + sAof + (uint32_t)(i * 16 * ASTR),
                 gB + k0 + (size_t)(i * 16) * Dq);
        cp_commit();
    };

    load_stage(0);
    load_stage(1);

    for (int c = 0; c < NCHUNK; c++) {
        if (c + 1 < NCHUNK) cp_wait<1>(); else cp_wait<0>();
        __syncthreads();

        const uint32_t stageBase = sbase + (uint32_t)((c & 1) * STAGE_BYTES);
#pragma unroll
        for (int s = 0; s < 4; s++) {               // four k32 steps per chunk
            const uint32_t k0 = s * 32;
            uint32_t af[2][4];
#pragma unroll
            for (int mb = 0; mb < 2; mb++)
                ldsm4(af[mb], stageBase + aoff[mb] + k0);
            uint32_t bf[4];
            ldsm4(bf, stageBase + boff + k0);
#pragma unroll
            for (int mb = 0; mb < 2; mb++) {
                mma_e4m3(acc[mb][0], af[mb], bf[0], bf[1]);
                mma_e4m3(acc[mb][1], af[mb], bf[2], bf[3]);
            }
        }
        __syncthreads();
        if (c + 2 < NCHUNK) load_stage(c + 2);
    }

    if (MODE == 0) {
        uint8_t* __restrict__ dst = g_T8 + (size_t)b * Dq * Dq;
#pragma unroll
        for (int mb = 0; mb < 2; mb++) {
            int r0 = rowBase + wm * 32 + mb * 16 + (lane >> 2);
#pragma unroll
            for (int nb = 0; nb < 2; nb++) {
                int col = colBase + wn * 16 + nb * 8 + (lane & 3) * 2;
                *(uint16_t*)(dst + (size_t)r0 * Dq + col) =
                    cvt2_e4m3(acc[mb][nb][1], acc[mb][nb][0]);
                *(uint16_t*)(dst + (size_t)(r0 + 8) * Dq + col) =
                    cvt2_e4m3(acc[mb][nb][3], acc[mb][nb][2]);
            }
        }
    } else {
#pragma unroll
        for (int mb = 0; mb < 2; mb++) {
            float m0 = -CUDART_INF_F, m1 = -CUDART_INF_F;
#pragma unroll
            for (int nb = 0; nb < 2; nb++) {
                m0 = fmaxf(m0, fmaxf(acc[mb][nb][0], acc[mb][nb][1]));
                m1 = fmaxf(m1, fmaxf(acc[mb][nb][2], acc[mb][nb][3]));
            }
            m0 = fmaxf(m0, __shfl_xor_sync(0xffffffffu, m0, 1));
            m0 = fmaxf(m0, __shfl_xor_sync(0xffffffffu, m0, 2));
            m1 = fmaxf(m1, __shfl_xor_sync(0xffffffffu, m1, 1));
            m1 = fmaxf(m1, __shfl_xor_sync(0xffffffffu, m1, 2));
            if ((lane & 3) == 0) {
                int r0 = rowBase + wm * 32 + mb * 16 + (lane >> 2);
                atomicMaxF(&g_rowmax[b * Dq + r0], m0);
                atomicMaxF(&g_rowmax[b * Dq + r0 + 8], m1);
            }
        }
    }
}

// ---- softmax over tanh(rowmax/64) ------------------------------------------
__global__ __launch_bounds__(1024) void softmax_k(float* __restrict__ out) {
    const int b = blockIdx.x;
    const int t = threadIdx.x;
    __shared__ float smax[32];
    __shared__ float ssum[32];

    float v = tanhf(g_rowmax[b * Dq + t] * 0.015625f);
    float m = v;
#pragma unroll
    for (int o = 16; o > 0; o >>= 1) m = fmaxf(m, __shfl_xor_sync(0xffffffffu, m, o));
    if ((t & 31) == 0) smax[t >> 5] = m;
    __syncthreads();
    if (t < 32) {
        float x = smax[t];
#pragma unroll
        for (int o = 16; o > 0; o >>= 1) x = fmaxf(x, __shfl_xor_sync(0xffffffffu, x, o));
        smax[t] = x;
    }
    __syncthreads();
    const float M = smax[0];
    float e = expf(v - M);
    float s = e;
#pragma unroll
    for (int o = 16; o > 0; o >>= 1) s += __shfl_xor_sync(0xffffffffu, s, o);
    if ((t & 31) == 0) ssum[t >> 5] = s;
    __syncthreads();
    if (t < 32) {
        float x = ssum[t];
#pragma unroll
        for (int o = 16; o > 0; o >>= 1) x += __shfl_xor_sync(0xffffffffu, x, o);
        ssum[t] = x;
    }
    __syncthreads();
    out[b * Dq + t] = e / ssum[0];
}

// -----------------------------------------------------------------------------
extern "C" void kernel_launch(void* const* d_in, const int* in_sizes, int n_in,
                              void* d_out, int out_size) {
    const float* emb = (const float*)d_in[0];   // [B, D, N]
    const float* W   = (const float*)d_in[2];   // [D, D]
    float* out = (float*)d_out;                 // [B, N, 1]

    cudaFuncSetAttribute(fp8_gemm_k<0>, cudaFuncAttributeMaxDynamicSharedMemorySize, SMEM_TOTAL);
    cudaFuncSetAttribute(fp8_gemm_k<1>, cudaFuncAttributeMaxDynamicSharedMemorySize, SMEM_TOTAL);

    convert_W_k<<<Dq * Dq / 512, 256>>>(W);
    convert_E_k<<<dim3(32, 32, Bq), 256>>>(emb);

    dim3 grid(Dq / BN, Dq / BM, Bq);   // (32, 16, 16)
    fp8_gemm_k<0><<<grid, NT, SMEM_TOTAL>>>();
    fp8_gemm_k<1><<<grid, NT, SMEM_TOTAL>>>();
    softmax_k<<<Bq, 1024>>>(out);
}

// round 13
// speedup vs baseline: 1.0967x; 1.0967x over previous
#include <cuda_runtime.h>
#include <cuda_bf16.h>
#include <math_constants.h>
#include <cstdint>

#define Dq 1024
#define Bq 16
#define BM 64
#define BN 64
#define BKB 128                       // K bytes per chunk (full row)
#define NCHUNK (Dq / BKB)             // 8
#define ASTR 144                      // padded row stride (128B + 16B)
#define A_STAGE (BM * ASTR)           // 9216 B
#define B_STAGE (BN * ASTR)           // 9216 B
#define STAGE_BYTES (A_STAGE + B_STAGE)   // 18432 B
#define SMEM_TOTAL (2 * STAGE_BYTES)      // 36864 B
#define NT 128

// ---- scratch (__device__ globals) ------------------------------------------
__device__ uint8_t g_W8 [(size_t)Dq * Dq];            // (64*W)[d][k] e4m3
__device__ uint8_t g_ET8[(size_t)Bq * Dq * Dq];       // E^T[b][n][d] e4m3
__device__ uint8_t g_T8 [(size_t)Bq * Dq * Dq];       // 64*Tt[b][n][d] e4m3
__device__ float g_rowmax[Bq * Dq];

// ---- helpers ---------------------------------------------------------------
__device__ __forceinline__ uint32_t smem_u32(const void* p) {
    uint32_t a;
    asm("{ .reg .u64 t; cvta.to.shared.u64 t, %1; cvt.u32.u64 %0, t; }" : "=r"(a) : "l"(p));
    return a;
}
__device__ __forceinline__ void cp16(uint32_t s, const void* g) {
    asm volatile("cp.async.cg.shared.global [%0], [%1], 16;\n" :: "r"(s), "l"(g));
}
__device__ __forceinline__ void cp_commit() { asm volatile("cp.async.commit_group;\n"); }
template <int N> __device__ __forceinline__ void cp_wait() {
    asm volatile("cp.async.wait_group %0;\n" :: "n"(N));
}
__device__ __forceinline__ void ldsm4(uint32_t* r, uint32_t addr) {
    asm volatile("ldmatrix.sync.aligned.m8n8.x4.shared.b16 {%0,%1,%2,%3}, [%4];"
                 : "=r"(r[0]), "=r"(r[1]), "=r"(r[2]), "=r"(r[3]) : "r"(addr));
}
__device__ __forceinline__ void mma_e4m3(float* d, const uint32_t* a, uint32_t b0, uint32_t b1) {
    asm volatile("mma.sync.aligned.m16n8k32.row.col.f32.e4m3.e4m3.f32 "
                 "{%0,%1,%2,%3}, {%4,%5,%6,%7}, {%8,%9}, {%0,%1,%2,%3};"
                 : "+f"(d[0]), "+f"(d[1]), "+f"(d[2]), "+f"(d[3])
                 : "r"(a[0]), "r"(a[1]), "r"(a[2]), "r"(a[3]), "r"(b0), "r"(b1));
}
__device__ __forceinline__ uint16_t cvt2_e4m3(float hi, float lo) {
    uint16_t r;
    asm("cvt.rn.satfinite.e4m3x2.f32 %0, %1, %2;" : "=h"(r) : "f"(hi), "f"(lo));
    return r;
}
__device__ __forceinline__ void atomicMaxF(float* addr, float val) {
    int old = __float_as_int(*addr);
    while (__int_as_float(old) < val) {
        int assumed = old;
        old = atomicCAS((int*)addr, assumed, __float_as_int(val));
        if (old == assumed) break;
    }
}

// ---- setup kernels ---------------------------------------------------------
// W fp32 -> e4m3 (x64); also initializes g_rowmax (grid covers it)
__global__ void convert_W_k(const float* __restrict__ W) {
    int i = blockIdx.x * 256 + threadIdx.x;
    float2 v = ((const float2*)W)[i];
    ((uint16_t*)g_W8)[i] = cvt2_e4m3(v.y * 64.f, v.x * 64.f);
    if (i < Bq * Dq) g_rowmax[i] = -CUDART_INF_F;
}
// E [b][d][n] fp32 -> g_ET8 [b][n][d] e4m3 (transpose via smem; float4 loads)
__global__ __launch_bounds__(256) void convert_E_k(const float* __restrict__ E) {
    __shared__ float tile[32][33];
    const int b = blockIdx.z;
    const int x0 = blockIdx.x * 32, y0 = blockIdx.y * 32;  // x = n, y = d
    const float* __restrict__ Eb = E + (size_t)b * Dq * Dq;
    const int t = threadIdx.x;
    {   // 256 threads x 1 float4 = 1024 elems (32x32 tile)
        const int y = t >> 3;          // 0..31
        const int x4 = (t & 7) * 4;    // 0..28
        float4 v = *(const float4*)(&Eb[(size_t)(y0 + y) * Dq + x0 + x4]);
        tile[y][x4 + 0] = v.x;
        tile[y][x4 + 1] = v.y;
        tile[y][x4 + 2] = v.z;
        tile[y][x4 + 3] = v.w;
    }
    __syncthreads();
    const int n = x0 + (t >> 3);
    const int d0 = (t & 7) * 4;
    float v0 = tile[d0 + 0][t >> 3], v1 = tile[d0 + 1][t >> 3];
    float v2 = tile[d0 + 2][t >> 3], v3 = tile[d0 + 3][t >> 3];
    uint32_t packed = (uint32_t)cvt2_e4m3(v1, v0) | ((uint32_t)cvt2_e4m3(v3, v2) << 16);
    *(uint32_t*)(g_ET8 + (size_t)b * Dq * Dq + (size_t)n * Dq + y0 + d0) = packed;
}

// ---- fp8 tensor-core GEMM (R10 configuration — measured optimum) -----------
// 128 threads, warp grid 2(M) x 2(N), warp tile 32 x 32, CTA tile 64 x 64.
// 2-stage double buffer; 6 CTAs/SM (24 warps).
// MODE 0: C = ET[b] @ (64W)^T  -> g_T8 (e4m3)
// MODE 1: C = ET[b] @ T8[b]^T  -> fused rowmax
template <int MODE>
__global__ __launch_bounds__(NT, 6) void fp8_gemm_k() {
    extern __shared__ char smem[];
    const uint32_t sbase = smem_u32(smem);
    const int t = threadIdx.x, lane = t & 31, wid = t >> 5;
    const int wm = wid >> 1, wn = wid & 1;          // 2(M) x 2(N)
    const int b = blockIdx.z;
    const int rowBase = blockIdx.y * BM;
    const int colBase = blockIdx.x * BN;

    const uint8_t* __restrict__ A = g_ET8 + (size_t)b * Dq * Dq;
    const uint8_t* __restrict__ Bm =
        (MODE == 0) ? g_W8 : (g_T8 + (size_t)b * Dq * Dq);

    float acc[2][4][4];
#pragma unroll
    for (int mb = 0; mb < 2; mb++)
#pragma unroll
        for (int nb = 0; nb < 4; nb++)
#pragma unroll
            for (int r = 0; r < 4; r++) acc[mb][nb][r] = 0.f;

    // hoisted fragment smem offsets (within a stage)
    uint32_t aoff[2], boff[2];
#pragma unroll
    for (int mb = 0; mb < 2; mb++)
        aoff[mb] = (uint32_t)((wm * 32 + mb * 16 + (lane & 15)) * ASTR + (lane >> 4) * 16);
#pragma unroll
    for (int p = 0; p < 2; p++)
        boff[p] = (uint32_t)((wn * 32 + p * 16 + ((lane >> 4) << 3) + (lane & 7)) * ASTR
                             + ((lane >> 3) & 1) * 16) + A_STAGE;

    // global load pointers (16B per cp16; 4 A rows + 4 B rows per thread)
    const uint8_t* gA = A + (size_t)(rowBase + (t >> 3)) * Dq + (t & 7) * 16;
    const uint8_t* gB = Bm + (size_t)(colBase + (t >> 3)) * Dq + (t & 7) * 16;
    const uint32_t sAof = (uint32_t)((t >> 3) * ASTR + (t & 7) * 16);

    auto load_stage = [&](int c) {
        const uint32_t sS = sbase + (uint32_t)((c & 1) * STAGE_BYTES);
        const size_t k0 = (size_t)c * BKB;
#pragma unroll
        for (int i = 0; i < 4; i++)                 // A: 64 rows x 8 x 16B
            cp16(sS + sAof + (uint32_t)(i * 16 * ASTR), gA + k0 + (size_t)(i * 16) * Dq);
#pragma unroll
        for (int i = 0; i < 4; i++)                 // B: 64 rows x 8 x 16B
            cp16(sS + A_STAGE + sAof + (uint32_t)(i * 16 * ASTR),
                 gB + k0 + (size_t)(i * 16) * Dq);
        cp_commit();
    };

    load_stage(0);
    load_stage(1);

    for (int c = 0; c < NCHUNK; c++) {
        if (c + 1 < NCHUNK) cp_wait<1>(); else cp_wait<0>();
        __syncthreads();

        const uint32_t stageBase = sbase + (uint32_t)((c & 1) * STAGE_BYTES);
#pragma unroll
        for (int s = 0; s < 4; s++) {               // four k32 steps per chunk
            const uint32_t k0 = s * 32;
            uint32_t af[2][4];
#pragma unroll
            for (int mb = 0; mb < 2; mb++)
                ldsm4(af[mb], stageBase + aoff[mb] + k0);
#pragma unroll
            for (int p = 0; p < 2; p++) {
                uint32_t bf[4];
                ldsm4(bf, stageBase + boff[p] + k0);
#pragma unroll
                for (int mb = 0; mb < 2; mb++) {
                    mma_e4m3(acc[mb][2 * p + 0], af[mb], bf[0], bf[1]);
                    mma_e4m3(acc[mb][2 * p + 1], af[mb], bf[2], bf[3]);
                }
            }
        }
        __syncthreads();
        if (c + 2 < NCHUNK) load_stage(c + 2);
    }

    if (MODE == 0) {
        uint8_t* __restrict__ dst = g_T8 + (size_t)b * Dq * Dq;
#pragma unroll
        for (int mb = 0; mb < 2; mb++) {
            int r0 = rowBase + wm * 32 + mb * 16 + (lane >> 2);
#pragma unroll
            for (int nb = 0; nb < 4; nb++) {
                int col = colBase + wn * 32 + nb * 8 + (lane & 3) * 2;
                *(uint16_t*)(dst + (size_t)r0 * Dq + col) =
                    cvt2_e4m3(acc[mb][nb][1], acc[mb][nb][0]);
                *(uint16_t*)(dst + (size_t)(r0 + 8) * Dq + col) =
                    cvt2_e4m3(acc[mb][nb][3], acc[mb][nb][2]);
            }
        }
    } else {
#pragma unroll
        for (int mb = 0; mb < 2; mb++) {
            float m0 = -CUDART_INF_F, m1 = -CUDART_INF_F;
#pragma unroll
            for (int nb = 0; nb < 4; nb++) {
                m0 = fmaxf(m0, fmaxf(acc[mb][nb][0], acc[mb][nb][1]));
                m1 = fmaxf(m1, fmaxf(acc[mb][nb][2], acc[mb][nb][3]));
            }
            m0 = fmaxf(m0, __shfl_xor_sync(0xffffffffu, m0, 1));
            m0 = fmaxf(m0, __shfl_xor_sync(0xffffffffu, m0, 2));
            m1 = fmaxf(m1, __shfl_xor_sync(0xffffffffu, m1, 1));
            m1 = fmaxf(m1, __shfl_xor_sync(0xffffffffu, m1, 2));
            if ((lane & 3) == 0) {
                int r0 = rowBase + wm * 32 + mb * 16 + (lane >> 2);
                atomicMaxF(&g_rowmax[b * Dq + r0], m0);
                atomicMaxF(&g_rowmax[b * Dq + r0 + 8], m1);
            }
        }
    }
}

// ---- softmax over tanh(rowmax/64) ------------------------------------------
__global__ __launch_bounds__(1024) void softmax_k(float* __restrict__ out) {
    const int b = blockIdx.x;
    const int t = threadIdx.x;
    __shared__ float smax[32];
    __shared__ float ssum[32];

    float v = tanhf(g_rowmax[b * Dq + t] * 0.015625f);
    float m = v;
#pragma unroll
    for (int o = 16; o > 0; o >>= 1) m = fmaxf(m, __shfl_xor_sync(0xffffffffu, m, o));
    if ((t & 31) == 0) smax[t >> 5] = m;
    __syncthreads();
    if (t < 32) {
        float x = smax[t];
#pragma unroll
        for (int o = 16; o > 0; o >>= 1) x = fmaxf(x, __shfl_xor_sync(0xffffffffu, x, o));
        smax[t] = x;
    }
    __syncthreads();
    const float M = smax[0];
    float e = expf(v - M);
    float s = e;
#pragma unroll
    for (int o = 16; o > 0; o >>= 1) s += __shfl_xor_sync(0xffffffffu, s, o);
    if ((t & 31) == 0) ssum[t >> 5] = s;
    __syncthreads();
    if (t < 32) {
        float x = ssum[t];
#pragma unroll
        for (int o = 16; o > 0; o >>= 1) x += __shfl_xor_sync(0xffffffffu, x, o);
        ssum[t] = x;
    }
    __syncthreads();
    out[b * Dq + t] = e / ssum[0];
}

// -----------------------------------------------------------------------------
extern "C" void kernel_launch(void* const* d_in, const int* in_sizes, int n_in,
                              void* d_out, int out_size) {
    const float* emb = (const float*)d_in[0];   // [B, D, N]
    const float* W   = (const float*)d_in[2];   // [D, D]
    float* out = (float*)d_out;                 // [B, N, 1]

    cudaFuncSetAttribute(fp8_gemm_k<0>, cudaFuncAttributeMaxDynamicSharedMemorySize, SMEM_TOTAL);
    cudaFuncSetAttribute(fp8_gemm_k<1>, cudaFuncAttributeMaxDynamicSharedMemorySize, SMEM_TOTAL);

    convert_W_k<<<Dq * Dq / 512, 256>>>(W);
    convert_E_k<<<dim3(32, 32, Bq), 256>>>(emb);

    dim3 grid(Dq / BN, Dq / BM, Bq);   // (16, 16, 16)
    fp8_gemm_k<0><<<grid, NT, SMEM_TOTAL>>>();
    fp8_gemm_k<1><<<grid, NT, SMEM_TOTAL>>>();
    softmax_k<<<Bq, 1024>>>(out);
}

// round 15
// speedup vs baseline: 1.1718x; 1.0685x over previous
#include <cuda_runtime.h>
#include <cuda_bf16.h>
#include <cuda_fp16.h>
#include <math_constants.h>
#include <cstdint>

#define Dq 1024
#define Bq 16
#define BM 64
#define BN 64
#define BKB 128                       // K bytes per chunk (full row)
#define NCHUNK (Dq / BKB)             // 8
#define ASTR 144                      // padded row stride (128B + 16B)
#define A_STAGE (BM * ASTR)           // 9216 B
#define B_STAGE (BN * ASTR)           // 9216 B
#define STAGE_BYTES (A_STAGE + B_STAGE)   // 18432 B
#define SMEM_TOTAL (2 * STAGE_BYTES)      // 36864 B
#define NT 128

// ---- scratch (__device__ globals) ------------------------------------------
__device__ uint8_t g_W8 [(size_t)Dq * Dq];            // (64*W)[d][k] e4m3
__device__ uint8_t g_ET8[(size_t)Bq * Dq * Dq];       // E^T[b][n][d] e4m3
__device__ uint8_t g_T8 [(size_t)Bq * Dq * Dq];       // 64*Tt[b][n][d] e4m3
__device__ float g_rowmax[Bq * Dq];

// ---- helpers ---------------------------------------------------------------
__device__ __forceinline__ uint32_t smem_u32(const void* p) {
    uint32_t a;
    asm("{ .reg .u64 t; cvta.to.shared.u64 t, %1; cvt.u32.u64 %0, t; }" : "=r"(a) : "l"(p));
    return a;
}
__device__ __forceinline__ void cp16(uint32_t s, const void* g) {
    asm volatile("cp.async.cg.shared.global [%0], [%1], 16;\n" :: "r"(s), "l"(g));
}
__device__ __forceinline__ void cp_commit() { asm volatile("cp.async.commit_group;\n"); }
template <int N> __device__ __forceinline__ void cp_wait() {
    asm volatile("cp.async.wait_group %0;\n" :: "n"(N));
}
__device__ __forceinline__ void ldsm4(uint32_t* r, uint32_t addr) {
    asm volatile("ldmatrix.sync.aligned.m8n8.x4.shared.b16 {%0,%1,%2,%3}, [%4];"
                 : "=r"(r[0]), "=r"(r[1]), "=r"(r[2]), "=r"(r[3]) : "r"(addr));
}
// fp8 MMA with f16 accumulators: 2 b32 regs hold 4 f16 (rows r / r+8, col pair)
__device__ __forceinline__ void mma_e4m3_h(uint32_t* d, const uint32_t* a,
                                           uint32_t b0, uint32_t b1) {
    asm volatile("mma.sync.aligned.m16n8k32.row.col.f16.e4m3.e4m3.f16 "
                 "{%0,%1}, {%2,%3,%4,%5}, {%6,%7}, {%0,%1};"
                 : "+r"(d[0]), "+r"(d[1])
                 : "r"(a[0]), "r"(a[1]), "r"(a[2]), "r"(a[3]), "r"(b0), "r"(b1));
}
__device__ __forceinline__ uint16_t cvt2_e4m3(float hi, float lo) {
    uint16_t r;
    asm("cvt.rn.satfinite.e4m3x2.f32 %0, %1, %2;" : "=h"(r) : "f"(hi), "f"(lo));
    return r;
}
__device__ __forceinline__ uint16_t cvt_e4m3x2_h2(uint32_t h2) {
    uint16_t r;
    asm("cvt.rn.satfinite.e4m3x2.f16x2 %0, %1;" : "=h"(r) : "r"(h2));
    return r;
}
__device__ __forceinline__ void atomicMaxF(float* addr, float val) {
    int old = __float_as_int(*addr);
    while (__int_as_float(old) < val) {
        int assumed = old;
        old = atomicCAS((int*)addr, assumed, __float_as_int(val));
        if (old == assumed) break;
    }
}

// ---- setup kernels ---------------------------------------------------------
__global__ void convert_W_k(const float* __restrict__ W) {
    int i = blockIdx.x * 256 + threadIdx.x;
    float2 v = ((const float2*)W)[i];
    ((uint16_t*)g_W8)[i] = cvt2_e4m3(v.y * 64.f, v.x * 64.f);
    if (i < Bq * Dq) g_rowmax[i] = -CUDART_INF_F;
}
__global__ __launch_bounds__(256) void convert_E_k(const float* __restrict__ E) {
    __shared__ float tile[32][33];
    const int b = blockIdx.z;
    const int x0 = blockIdx.x * 32, y0 = blockIdx.y * 32;
    const float* __restrict__ Eb = E + (size_t)b * Dq * Dq;
    const int t = threadIdx.x;
    {
        const int y = t >> 3;
        const int x4 = (t & 7) * 4;
        float4 v = *(const float4*)(&Eb[(size_t)(y0 + y) * Dq + x0 + x4]);
        tile[y][x4 + 0] = v.x;
        tile[y][x4 + 1] = v.y;
        tile[y][x4 + 2] = v.z;
        tile[y][x4 + 3] = v.w;
    }
    __syncthreads();
    const int n = x0 + (t >> 3);
    const int d0 = (t & 7) * 4;
    float v0 = tile[d0 + 0][t >> 3], v1 = tile[d0 + 1][t >> 3];
    float v2 = tile[d0 + 2][t >> 3], v3 = tile[d0 + 3][t >> 3];
    uint32_t packed = (uint32_t)cvt2_e4m3(v1, v0) | ((uint32_t)cvt2_e4m3(v3, v2) << 16);
    *(uint32_t*)(g_ET8 + (size_t)b * Dq * Dq + (size_t)n * Dq + y0 + d0) = packed;
}

// ---- fp8 tensor-core GEMM (R10 tiling; f16 accumulators) --------------------
// 128 threads, warp grid 2x2, warp tile 32x32, CTA tile 64x64, 6 CTAs/SM.
// MODE 0: C = ET[b] @ (64W)^T  -> g_T8 (e4m3)
// MODE 1: C = ET[b] @ T8[b]^T  -> fused rowmax
template <int MODE>
__global__ __launch_bounds__(NT, 6) void fp8_gemm_k() {
    extern __shared__ char smem[];
    const uint32_t sbase = smem_u32(smem);
    const int t = threadIdx.x, lane = t & 31, wid = t >> 5;
    const int wm = wid >> 1, wn = wid & 1;
    const int b = blockIdx.z;
    const int rowBase = blockIdx.y * BM;
    const int colBase = blockIdx.x * BN;

    const uint8_t* __restrict__ A = g_ET8 + (size_t)b * Dq * Dq;
    const uint8_t* __restrict__ Bm =
        (MODE == 0) ? g_W8 : (g_T8 + (size_t)b * Dq * Dq);

    uint32_t acc[2][4][2];   // f16x2 accumulators: [mb][nb][row r / r+8]
#pragma unroll
    for (int mb = 0; mb < 2; mb++)
#pragma unroll
        for (int nb = 0; nb < 4; nb++) { acc[mb][nb][0] = 0u; acc[mb][nb][1] = 0u; }

    uint32_t aoff[2], boff[2];
#pragma unroll
    for (int mb = 0; mb < 2; mb++)
        aoff[mb] = (uint32_t)((wm * 32 + mb * 16 + (lane & 15)) * ASTR + (lane >> 4) * 16);
#pragma unroll
    for (int p = 0; p < 2; p++)
        boff[p] = (uint32_t)((wn * 32 + p * 16 + ((lane >> 4) << 3) + (lane & 7)) * ASTR
                             + ((lane >> 3) & 1) * 16) + A_STAGE;

    const uint8_t* gA = A + (size_t)(rowBase + (t >> 3)) * Dq + (t & 7) * 16;
    const uint8_t* gB = Bm + (size_t)(colBase + (t >> 3)) * Dq + (t & 7) * 16;
    const uint32_t sAof = (uint32_t)((t >> 3) * ASTR + (t & 7) * 16);

    auto load_stage = [&](int c) {
        const uint32_t sS = sbase + (uint32_t)((c & 1) * STAGE_BYTES);
        const size_t k0 = (size_t)c * BKB;
#pragma unroll
        for (int i = 0; i < 4; i++)
            cp16(sS + sAof + (uint32_t)(i * 16 * ASTR), gA + k0 + (size_t)(i * 16) * Dq);
#pragma unroll
        for (int i = 0; i < 4; i++)
            cp16(sS + A_STAGE + sAof + (uint32_t)(i * 16 * ASTR),
                 gB + k0 + (size_t)(i * 16) * Dq);
        cp_commit();
    };

    load_stage(0);
    load_stage(1);

    for (int c = 0; c < NCHUNK; c++) {
        if (c + 1 < NCHUNK) cp_wait<1>(); else cp_wait<0>();
        __syncthreads();

        const uint32_t stageBase = sbase + (uint32_t)((c & 1) * STAGE_BYTES);
#pragma unroll
        for (int s = 0; s < 4; s++) {
            const uint32_t k0 = s * 32;
            uint32_t af[2][4];
#pragma unroll
            for (int mb = 0; mb < 2; mb++)
                ldsm4(af[mb], stageBase + aoff[mb] + k0);
#pragma unroll
            for (int p = 0; p < 2; p++) {
                uint32_t bf[4];
                ldsm4(bf, stageBase + boff[p] + k0);
#pragma unroll
                for (int mb = 0; mb < 2; mb++) {
                    mma_e4m3_h(acc[mb][2 * p + 0], af[mb], bf[0], bf[1]);
                    mma_e4m3_h(acc[mb][2 * p + 1], af[mb], bf[2], bf[3]);
                }
            }
        }
        __syncthreads();
        if (c + 2 < NCHUNK) load_stage(c + 2);
    }

    if (MODE == 0) {
        uint8_t* __restrict__ dst = g_T8 + (size_t)b * Dq * Dq;
#pragma unroll
        for (int mb = 0; mb < 2; mb++) {
            int r0 = rowBase + wm * 32 + mb * 16 + (lane >> 2);
#pragma unroll
            for (int nb = 0; nb < 4; nb++) {
                int col = colBase + wn * 32 + nb * 8 + (lane & 3) * 2;
                *(uint16_t*)(dst + (size_t)r0 * Dq + col) = cvt_e4m3x2_h2(acc[mb][nb][0]);
                *(uint16_t*)(dst + (size_t)(r0 + 8) * Dq + col) = cvt_e4m3x2_h2(acc[mb][nb][1]);
            }
        }
    } else {
#pragma unroll
        for (int mb = 0; mb < 2; mb++) {
            __half2 h0 = *(__half2*)&acc[mb][0][0];
            __half2 h1 = *(__half2*)&acc[mb][0][1];
#pragma unroll
            for (int nb = 1; nb < 4; nb++) {
                h0 = __hmax2(h0, *(__half2*)&acc[mb][nb][0]);
                h1 = __hmax2(h1, *(__half2*)&acc[mb][nb][1]);
            }
            float m0 = fmaxf(__low2float(h0), __high2float(h0));
            float m1 = fmaxf(__low2float(h1), __high2float(h1));
            m0 = fmaxf(m0, __shfl_xor_sync(0xffffffffu, m0, 1));
            m0 = fmaxf(m0, __shfl_xor_sync(0xffffffffu, m0, 2));
            m1 = fmaxf(m1, __shfl_xor_sync(0xffffffffu, m1, 1));
            m1 = fmaxf(m1, __shfl_xor_sync(0xffffffffu, m1, 2));
            if ((lane & 3) == 0) {
                int r0 = rowBase + wm * 32 + mb * 16 + (lane >> 2);
                atomicMaxF(&g_rowmax[b * Dq + r0], m0);
                atomicMaxF(&g_rowmax[b * Dq + r0 + 8], m1);
            }
        }
    }
}

// ---- softmax over tanh(rowmax/64) ------------------------------------------
__global__ __launch_bounds__(1024) void softmax_k(float* __restrict__ out) {
    const int b = blockIdx.x;
    const int t = threadIdx.x;
    __shared__ float smax[32];
    __shared__ float ssum[32];

    float v = tanhf(g_rowmax[b * Dq + t] * 0.015625f);
    float m = v;
#pragma unroll
    for (int o = 16; o > 0; o >>= 1) m = fmaxf(m, __shfl_xor_sync(0xffffffffu, m, o));
    if ((t & 31) == 0) smax[t >> 5] = m;
    __syncthreads();
    if (t < 32) {
        float x = smax[t];
#pragma unroll
        for (int o = 16; o > 0; o >>= 1) x = fmaxf(x, __shfl_xor_sync(0xffffffffu, x, o));
        smax[t] = x;
    }
    __syncthreads();
    const float M = smax[0];
    float e = expf(v - M);
    float s = e;
#pragma unroll
    for (int o = 16; o > 0; o >>= 1) s += __shfl_xor_sync(0xffffffffu, s, o);
    if ((t & 31) == 0) ssum[t >> 5] = s;
    __syncthreads();
    if (t < 32) {
        float x = ssum[t];
#pragma unroll
        for (int o = 16; o > 0; o >>= 1) x += __shfl_xor_sync(0xffffffffu, x, o);
        ssum[t] = x;
    }
    __syncthreads();
    out[b * Dq + t] = e / ssum[0];
}

// -----------------------------------------------------------------------------
extern "C" void kernel_launch(void* const* d_in, const int* in_sizes, int n_in,
                              void* d_out, int out_size) {
    const float* emb = (const float*)d_in[0];   // [B, D, N]
    const float* W   = (const float*)d_in[2];   // [D, D]
    float* out = (float*)d_out;                 // [B, N, 1]

    cudaFuncSetAttribute(fp8_gemm_k<0>, cudaFuncAttributeMaxDynamicSharedMemorySize, SMEM_TOTAL);
    cudaFuncSetAttribute(fp8_gemm_k<1>, cudaFuncAttributeMaxDynamicSharedMemorySize, SMEM_TOTAL);

    convert_W_k<<<Dq * Dq / 512, 256>>>(W);
    convert_E_k<<<dim3(32, 32, Bq), 256>>>(emb);

    dim3 grid(Dq / BN, Dq / BM, Bq);   // (16, 16, 16)
    fp8_gemm_k<0><<<grid, NT, SMEM_TOTAL>>>();
    fp8_gemm_k<1><<<grid, NT, SMEM_TOTAL>>>();
    softmax_k<<<Bq, 1024>>>(out);
}